// round 1
// baseline (speedup 1.0000x reference)
#include <cuda_runtime.h>

#define TLEN 65536
#define INPD 5
#define HD 100
#define G4 400            // 4*HD
#define XG_TILE 16

// Scratch (static device arrays; no runtime allocation allowed)
__device__ float g_xg[(size_t)TLEN * G4];   // input-projection gates for current layer
__device__ float g_h1[(size_t)TLEN * HD];   // layer-0 hidden outputs
__device__ float g_h2[(size_t)TLEN * HD];   // layer-1 hidden outputs

// ---------- helpers ----------
__device__ __forceinline__ unsigned long long ffma2(unsigned long long a,
                                                    unsigned long long b,
                                                    unsigned long long c) {
    unsigned long long d;
    asm("fma.rn.f32x2 %0, %1, %2, %3;" : "=l"(d) : "l"(a), "l"(b), "l"(c));
    return d;
}
__device__ __forceinline__ float2 unpack2(unsigned long long v) {
    float2 r;
    asm("mov.b64 {%0, %1}, %2;" : "=f"(r.x), "=f"(r.y) : "l"(v));
    return r;
}
__device__ __forceinline__ float fsigmoid(float x) {
    return __fdividef(1.f, 1.f + __expf(-x));
}
__device__ __forceinline__ float ftanh_(float x) {
    x = fminf(15.f, fmaxf(-15.f, x));
    float e = __expf(2.f * x);
    return __fdividef(e - 1.f, e + 1.f);
}

// ---------- phase 1: xg0 = Wih0 @ x[t] + bih0 + bhh0 ----------
__global__ void xg0_kernel(const float* __restrict__ x,
                           const float* __restrict__ Wih0,
                           const float* __restrict__ bih0,
                           const float* __restrict__ bhh0) {
    int g = threadIdx.x;                 // 0..399
    int t0 = blockIdx.x * XG_TILE;
    float w0 = __ldg(Wih0 + g * INPD + 0);
    float w1 = __ldg(Wih0 + g * INPD + 1);
    float w2 = __ldg(Wih0 + g * INPD + 2);
    float w3 = __ldg(Wih0 + g * INPD + 3);
    float w4 = __ldg(Wih0 + g * INPD + 4);
    float b = __ldg(bih0 + g) + __ldg(bhh0 + g);
#pragma unroll
    for (int tt = 0; tt < XG_TILE; tt++) {
        const float* xr = x + (size_t)(t0 + tt) * INPD;
        float acc = b;
        acc = __fmaf_rn(w0, __ldg(xr + 0), acc);
        acc = __fmaf_rn(w1, __ldg(xr + 1), acc);
        acc = __fmaf_rn(w2, __ldg(xr + 2), acc);
        acc = __fmaf_rn(w3, __ldg(xr + 3), acc);
        acc = __fmaf_rn(w4, __ldg(xr + 4), acc);
        g_xg[(size_t)(t0 + tt) * G4 + g] = acc;
    }
}

// ---------- phase 3: xg1 = Wih1 @ h1[t] + bih1 + bhh1 ----------
__global__ void xg1_kernel(const float* __restrict__ Wih1,
                           const float* __restrict__ bih1,
                           const float* __restrict__ bhh1) {
    __shared__ __align__(16) float hs[XG_TILE][HD];
    int t0 = blockIdx.x * XG_TILE;
    for (int i = threadIdx.x; i < XG_TILE * HD; i += blockDim.x)
        hs[i / HD][i % HD] = g_h1[(size_t)t0 * HD + i];
    __syncthreads();

    int g = threadIdx.x;                 // 0..399
    float b = __ldg(bih1 + g) + __ldg(bhh1 + g);
    float acc[XG_TILE];
#pragma unroll
    for (int tt = 0; tt < XG_TILE; tt++) acc[tt] = b;

    const float4* wr = (const float4*)(Wih1 + (size_t)g * HD);
#pragma unroll
    for (int k = 0; k < HD / 4; k++) {
        float4 wv = __ldg(wr + k);
#pragma unroll
        for (int tt = 0; tt < XG_TILE; tt++) {
            float4 hv = *(const float4*)&hs[tt][4 * k];
            acc[tt] = __fmaf_rn(wv.x, hv.x, acc[tt]);
            acc[tt] = __fmaf_rn(wv.y, hv.y, acc[tt]);
            acc[tt] = __fmaf_rn(wv.z, hv.z, acc[tt]);
            acc[tt] = __fmaf_rn(wv.w, hv.w, acc[tt]);
        }
    }
#pragma unroll
    for (int tt = 0; tt < XG_TILE; tt++)
        g_xg[(size_t)(t0 + tt) * G4 + g] = acc[tt];
}

// ---------- serial recurrence: one persistent block, thread g = gate g ----------
__global__ __launch_bounds__(G4, 1)
void lstm_rec_kernel(const float* __restrict__ Whh,
                     const float* __restrict__ xg,
                     float* __restrict__ h_out) {
    __shared__ __align__(16) float h_s[HD];
    __shared__ float gate_s[G4];

    int g = threadIdx.x;                 // 0..399
    int type = g / HD;                   // 0:i 1:f 2:g 3:o

    // Whh row g -> registers, pre-packed as f32x2 (bit layout matches two floats)
    unsigned long long w[HD / 2];
    {
        const ulonglong2* wr = (const ulonglong2*)(Whh + (size_t)g * HD);
#pragma unroll
        for (int k = 0; k < HD / 4; k++) {
            ulonglong2 v = wr[k];
            w[2 * k] = v.x;
            w[2 * k + 1] = v.y;
        }
    }

    if (g < HD) h_s[g] = 0.f;
    float c = 0.f;
    __syncthreads();

    const ulonglong2* hp = (const ulonglong2*)h_s;
    const float* xp = xg + g;

    // prefetch xg two steps ahead to hide DRAM latency off the critical path
    float xv0 = __ldcs(xp);
    float xv1 = __ldcs(xp + G4);

    for (int t = 0; t < TLEN; t++) {
        float xv = xv0;
        xv0 = xv1;
        int tn = (t + 2 < TLEN) ? (t + 2) : (TLEN - 1);
        xv1 = __ldcs(xp + (size_t)tn * G4);

        unsigned long long a0 = 0ull, a1 = 0ull, a2 = 0ull, a3 = 0ull;
#pragma unroll
        for (int k = 0; k < HD / 4; k++) {       // 25 x LDS.128 + 50 x FFMA2
            ulonglong2 hv = hp[k];
            if (k & 1) {
                a2 = ffma2(w[2 * k], hv.x, a2);
                a3 = ffma2(w[2 * k + 1], hv.y, a3);
            } else {
                a0 = ffma2(w[2 * k], hv.x, a0);
                a1 = ffma2(w[2 * k + 1], hv.y, a1);
            }
        }
        float2 s0 = unpack2(a0), s1 = unpack2(a1), s2 = unpack2(a2), s3 = unpack2(a3);
        float gv = ((s0.x + s0.y) + (s1.x + s1.y)) +
                   ((s2.x + s2.y) + (s3.x + s3.y)) + xv;

        float act = (type == 2) ? ftanh_(gv) : fsigmoid(gv);
        gate_s[g] = act;
        __syncthreads();

        if (g < HD) {
            float iv = gate_s[g];
            float fv = gate_s[g + HD];
            float gg = gate_s[g + 2 * HD];
            float ov = gate_s[g + 3 * HD];
            c = __fmaf_rn(fv, c, iv * gg);
            float h = ov * ftanh_(c);
            h_s[g] = h;
            __stcs(h_out + (size_t)t * HD + g, h);
        }
        __syncthreads();
    }
}

// ---------- phase 5: out[t] = sigmoid(h2[t] . Wlin + blin) ----------
__global__ void out_kernel(const float* __restrict__ Wlin,
                           const float* __restrict__ blin,
                           float* __restrict__ out) {
    int warp = (blockIdx.x * blockDim.x + threadIdx.x) >> 5;
    int lane = threadIdx.x & 31;
    if (warp >= TLEN) return;
    const float* hr = g_h2 + (size_t)warp * HD;
    float acc = 0.f;
#pragma unroll
    for (int k = 0; k < 4; k++) {
        int j = lane + 32 * k;
        if (j < HD) acc = __fmaf_rn(hr[j], __ldg(Wlin + j), acc);
    }
#pragma unroll
    for (int o = 16; o; o >>= 1) acc += __shfl_down_sync(0xffffffffu, acc, o);
    if (lane == 0) out[warp] = fsigmoid(acc + __ldg(blin));
}

// ---------- launch ----------
extern "C" void kernel_launch(void* const* d_in, const int* in_sizes, int n_in,
                              void* d_out, int out_size) {
    const float* x    = (const float*)d_in[0];
    const float* Wih0 = (const float*)d_in[1];
    const float* Whh0 = (const float*)d_in[2];
    const float* bih0 = (const float*)d_in[3];
    const float* bhh0 = (const float*)d_in[4];
    const float* Wih1 = (const float*)d_in[5];
    const float* Whh1 = (const float*)d_in[6];
    const float* bih1 = (const float*)d_in[7];
    const float* bhh1 = (const float*)d_in[8];
    const float* Wlin = (const float*)d_in[9];
    const float* blin = (const float*)d_in[10];
    float* out = (float*)d_out;

    void *xg_p = nullptr, *h1_p = nullptr, *h2_p = nullptr;
    cudaGetSymbolAddress(&xg_p, g_xg);
    cudaGetSymbolAddress(&h1_p, g_h1);
    cudaGetSymbolAddress(&h2_p, g_h2);

    xg0_kernel<<<TLEN / XG_TILE, G4>>>(x, Wih0, bih0, bhh0);
    lstm_rec_kernel<<<1, G4>>>(Whh0, (const float*)xg_p, (float*)h1_p);
    xg1_kernel<<<TLEN / XG_TILE, G4>>>(Wih1, bih1, bhh1);
    lstm_rec_kernel<<<1, G4>>>(Whh1, (const float*)xg_p, (float*)h2_p);
    out_kernel<<<(TLEN * 32) / 256, 256>>>(Wlin, blin, out);
}

// round 3
// speedup vs baseline: 2.1554x; 2.1554x over previous
#include <cuda_runtime.h>

#define TLEN 65536
#define INPD 5
#define HD 100
#define G4 400            // 4*HD
#define CHUNK 16
#define NCHUNK (TLEN / CHUNK)
#define XG_TILE 16

// ---------------- static device scratch ----------------
__device__ float g_xg0[(size_t)TLEN * G4];
__device__ float g_xg1[(size_t)TLEN * G4];
__device__ float g_h1[(size_t)TLEN * HD];
__device__ float g_h2[(size_t)TLEN * HD];
__device__ int   g_prog0;           // layer-0 chunks completed
__device__ int   g_ready[NCHUNK];   // xg1 chunk ready flags

// ---------------- helpers ----------------
typedef unsigned long long u64;

__device__ __forceinline__ u64 ffma2(u64 a, u64 b, u64 c) {
    u64 d;
    asm("fma.rn.f32x2 %0, %1, %2, %3;" : "=l"(d) : "l"(a), "l"(b), "l"(c));
    return d;
}
#define ONE2 0x3F8000003F800000ull
__device__ __forceinline__ u64 fadd2(u64 a, u64 b) {    // a + b via fma(a,1,b)
    return ffma2(a, ONE2, b);
}
__device__ __forceinline__ float2 unpack2(u64 v) {
    float2 r;
    asm("mov.b64 {%0, %1}, %2;" : "=f"(r.x), "=f"(r.y) : "l"(v));
    return r;
}
__device__ __forceinline__ float tanh_ap(float x) {
    float y;
    asm("tanh.approx.f32 %0, %1;" : "=f"(y) : "f"(x));
    return y;
}
__device__ __forceinline__ float sigmoid_ap(float x) {
    return __fmaf_rn(0.5f, tanh_ap(0.5f * x), 0.5f);
}

// 100-dot against registers w[50] (f32x2) and 16B-aligned smem vector
__device__ __forceinline__ float dot100(const u64* __restrict__ w, const float* __restrict__ hvec) {
    const ulonglong2* hp = (const ulonglong2*)hvec;
    u64 a0 = 0ull, a1 = 0ull, a2 = 0ull, a3 = 0ull;
#pragma unroll
    for (int k = 0; k < HD / 4; k++) {
        ulonglong2 hv = hp[k];
        if (k & 1) {
            a2 = ffma2(w[2 * k], hv.x, a2);
            a3 = ffma2(w[2 * k + 1], hv.y, a3);
        } else {
            a0 = ffma2(w[2 * k], hv.x, a0);
            a1 = ffma2(w[2 * k + 1], hv.y, a1);
        }
    }
    a0 = fadd2(a0, a1);
    a2 = fadd2(a2, a3);
    a0 = fadd2(a0, a2);
    float2 s = unpack2(a0);
    return s.x + s.y;
}

__device__ __forceinline__ void load_wrow(u64* w, const float* row) {
    const ulonglong2* wr = (const ulonglong2*)row;
#pragma unroll
    for (int k = 0; k < HD / 4; k++) {
        ulonglong2 v = wr[k];
        w[2 * k] = v.x;
        w[2 * k + 1] = v.y;
    }
}

// ---------------- phase 1: xg0 = Wih0 @ x[t] + bih0 + bhh0 (+ flag reset) ------
__global__ void xg0_kernel(const float* __restrict__ x,
                           const float* __restrict__ Wih0,
                           const float* __restrict__ bih0,
                           const float* __restrict__ bhh0) {
    int g = threadIdx.x;                 // 0..399
    if (blockIdx.x == 0) {               // reset cross-block flags for this run
        for (int i = g; i < NCHUNK; i += G4) g_ready[i] = 0;
        if (g == 0) g_prog0 = 0;
    }
    int t0 = blockIdx.x * XG_TILE;
    float w0 = __ldg(Wih0 + g * INPD + 0);
    float w1 = __ldg(Wih0 + g * INPD + 1);
    float w2 = __ldg(Wih0 + g * INPD + 2);
    float w3 = __ldg(Wih0 + g * INPD + 3);
    float w4 = __ldg(Wih0 + g * INPD + 4);
    float b = __ldg(bih0 + g) + __ldg(bhh0 + g);
#pragma unroll
    for (int tt = 0; tt < XG_TILE; tt++) {
        const float* xr = x + (size_t)(t0 + tt) * INPD;
        float acc = b;
        acc = __fmaf_rn(w0, __ldg(xr + 0), acc);
        acc = __fmaf_rn(w1, __ldg(xr + 1), acc);
        acc = __fmaf_rn(w2, __ldg(xr + 2), acc);
        acc = __fmaf_rn(w3, __ldg(xr + 3), acc);
        acc = __fmaf_rn(w4, __ldg(xr + 4), acc);
        g_xg0[(size_t)(t0 + tt) * G4 + g] = acc;
    }
}

// ---------------- recurrence body (one block, 400 threads) ----------------
// thread tid = 4*j + q  ->  unit j (0..99), gate q (0:i 1:f 2:g 3:o)
// weight row index = q*HD + j  (PyTorch i,f,g,o order)
// Each thread reads ONLY xg column `row`, so xg is prefetched straight into
// registers — no SMEM staging needed.
template <bool RELEASE, bool WAIT>
__device__ void rec_body(const float* __restrict__ Whh,
                         const float* __restrict__ xg,
                         float* __restrict__ hout,
                         float* __restrict__ h_s /* [2][HD], 16B-aligned smem */) {
    int tid = threadIdx.x;
    int j = tid >> 2, q = tid & 3;
    int row = q * HD + j;
    unsigned mask = __activemask();

    u64 w[HD / 2];
    load_wrow(w, Whh + (size_t)row * HD);

    if (q == 0) h_s[j] = 0.f;            // h_s[0][j]
    float c = 0.f;

    // prefetch chunk 0 into registers
    if (WAIT) {
        while (*((volatile int*)&g_ready[0]) == 0) __nanosleep(100);
        __threadfence();
    }
    float xr[CHUNK];
    {
        const float* xp = xg + row;
#pragma unroll
        for (int s = 0; s < CHUNK; s++) xr[s] = __ldcg(xp + (size_t)s * G4);
    }
    __syncthreads();

#pragma unroll 1
    for (int c0 = 0; c0 < NCHUNK; c0++) {
        float xc[CHUNK];
#pragma unroll
        for (int s = 0; s < CHUNK; s++) xc[s] = xr[s];

        if (c0 + 1 < NCHUNK) {       // prefetch next chunk (off critical path)
            if (WAIT) {
                while (*((volatile int*)&g_ready[c0 + 1]) == 0) __nanosleep(100);
                __threadfence();
            }
            const float* xp = xg + (size_t)(c0 + 1) * CHUNK * G4 + row;
#pragma unroll
            for (int s = 0; s < CHUNK; s++) xr[s] = __ldcg(xp + (size_t)s * G4);
        }

#pragma unroll 1
        for (int s = 0; s < CHUNK; s++) {
            int t = c0 * CHUNK + s;
            float gv = dot100(w, h_s + (t & 1) * HD) + xc[s];
            float act = (q == 2) ? tanh_ap(gv) : sigmoid_ap(gv);
            float fv = __shfl_down_sync(mask, act, 1, 4);
            float gg = __shfl_down_sync(mask, act, 2, 4);
            float ov = __shfl_down_sync(mask, act, 3, 4);
            if (q == 0) {
                c = __fmaf_rn(fv, c, act * gg);
                float h = ov * tanh_ap(c);
                h_s[((t + 1) & 1) * HD + j] = h;
                __stcg(hout + (size_t)t * HD + j, h);
            }
            __syncthreads();
        }

        if (RELEASE && tid == 0) {
            __threadfence();
            *((volatile int*)&g_prog0) = c0 + 1;
        }
    }
}

// ---------------- xg1 streaming body (2 blocks, alternate chunks) ----------------
__device__ void xg_body(const float* __restrict__ Wih1,
                        const float* __restrict__ bih1,
                        const float* __restrict__ bhh1, int b,
                        float* __restrict__ hbuf /* [CHUNK][HD] smem */) {
    int tid = threadIdx.x;

    u64 w[HD / 2];
    load_wrow(w, Wih1 + (size_t)tid * HD);
    float bb = __ldg(bih1 + tid) + __ldg(bhh1 + tid);

#pragma unroll 1
    for (int c0 = b; c0 < NCHUNK; c0 += 2) {
        while (*((volatile int*)&g_prog0) < c0 + 1) __nanosleep(200);
        __threadfence();
        __syncthreads();                 // protect hbuf reuse
        for (int i = tid; i < CHUNK * HD; i += G4)
            hbuf[i] = __ldcg(g_h1 + (size_t)c0 * CHUNK * HD + i);
        __syncthreads();

#pragma unroll 1
        for (int s = 0; s < CHUNK; s++) {
            float v = dot100(w, hbuf + s * HD) + bb;
            __stcg(g_xg1 + (size_t)(c0 * CHUNK + s) * G4 + tid, v);
        }
        __syncthreads();
        if (tid == 0) {
            __threadfence();
            *((volatile int*)&g_ready[c0]) = 1;
        }
    }
}

// ---------------- fused pipelined kernel: grid = 4 blocks ----------------
// Single shared pool reused by whichever body this block runs.
__global__ __launch_bounds__(G4, 1)
void fused_kernel(const float* __restrict__ Whh0,
                  const float* __restrict__ Whh1,
                  const float* __restrict__ Wih1,
                  const float* __restrict__ bih1,
                  const float* __restrict__ bhh1) {
    __shared__ __align__(16) float smem_pool[CHUNK * HD];  // 6400 B, fits all bodies
    int b = blockIdx.x;
    if (b == 0)
        rec_body<true, false>(Whh0, g_xg0, g_h1, smem_pool);
    else if (b <= 2)
        xg_body(Wih1, bih1, bhh1, b - 1, smem_pool);
    else
        rec_body<false, true>(Whh1, g_xg1, g_h2, smem_pool);
}

// ---------------- final linear + sigmoid ----------------
__global__ void out_kernel(const float* __restrict__ Wlin,
                           const float* __restrict__ blin,
                           float* __restrict__ out) {
    int warp = (blockIdx.x * blockDim.x + threadIdx.x) >> 5;
    int lane = threadIdx.x & 31;
    if (warp >= TLEN) return;
    const float* hr = g_h2 + (size_t)warp * HD;
    float acc = 0.f;
#pragma unroll
    for (int k = 0; k < 4; k++) {
        int idx = lane + 32 * k;
        if (idx < HD) acc = __fmaf_rn(hr[idx], __ldg(Wlin + idx), acc);
    }
#pragma unroll
    for (int o = 16; o; o >>= 1) acc += __shfl_down_sync(0xffffffffu, acc, o);
    if (lane == 0) out[warp] = sigmoid_ap(acc + __ldg(blin));
}

// ---------------- launch ----------------
extern "C" void kernel_launch(void* const* d_in, const int* in_sizes, int n_in,
                              void* d_out, int out_size) {
    const float* x    = (const float*)d_in[0];
    const float* Wih0 = (const float*)d_in[1];
    const float* Whh0 = (const float*)d_in[2];
    const float* bih0 = (const float*)d_in[3];
    const float* bhh0 = (const float*)d_in[4];
    const float* Wih1 = (const float*)d_in[5];
    const float* Whh1 = (const float*)d_in[6];
    const float* bih1 = (const float*)d_in[7];
    const float* bhh1 = (const float*)d_in[8];
    const float* Wlin = (const float*)d_in[9];
    const float* blin = (const float*)d_in[10];
    float* out = (float*)d_out;

    xg0_kernel<<<TLEN / XG_TILE, G4>>>(x, Wih0, bih0, bhh0);
    fused_kernel<<<4, G4>>>(Whh0, Whh1, Wih1, bih1, bhh1);
    out_kernel<<<(TLEN * 32) / 256, 256>>>(Wlin, blin, out);
}